// round 16
// baseline (speedup 1.0000x reference)
#include <cuda_runtime.h>
#include <cuda_bf16.h>
#include <cstdint>

// Problem constants (fixed by the reference)
#define NB 32      // batch
#define NZ 4000    // nodes
#define NIN 32     // in features
#define NH 64      // hidden
#define NE 64000   // edges

#define NY  (NB * NZ * NIN / 4)   // 1,024,000 float4 loads of x
#define NYB (NY / 1024)           // 1000 ydot blocks (1024 float4 per block)
#define NEB (NE / 256)            // 250 histogram blocks
#define NSB ((NE * 8) / 512)      // 1000 scatter blocks (2 float4 REDs/thread)

// Scratch (device globals; zero-initialized at module load).
// g_acc is fully OVERWRITTEN by k_ydot each execution (self-loop init);
// g_deg is re-zeroed by k_out after use.
__device__ __align__(16) float g_w[NZ * NB];    // w[z*NB+b] = dinv_z * (x[b,z,:].v)
__device__ __align__(16) float g_acc[NZ * NB];  // acc[z][b]: init w_z, + sum_{s->z} w_s
__device__ int g_deg[NZ];                       // in-degree EXCLUDING self-loop
__device__ __align__(16) float g_v[NIN];        // W @ fc_W
__device__ float g_const;                       // bias . fc_W + fc_b

// ---------------------------------------------------------------------------
// K1: degree histogram (blocks 0..NEB-1) + v/const (block NEB).
// Triggers programmatic launch completion at entry so K2 (ydot) can launch
// immediately and hide its x-load latency under the histogram.
// ---------------------------------------------------------------------------
__global__ void k_hist_v(const int* __restrict__ dst,
                         const float* __restrict__ W,
                         const float* __restrict__ bias,
                         const float* __restrict__ fcW,
                         const float* __restrict__ fcb) {
    cudaTriggerProgrammaticLaunchCompletion();
    const int tx = threadIdx.x;
    if (blockIdx.x < NEB) {
        int e = blockIdx.x * 256 + tx;
        atomicAdd(&g_deg[__ldg(&dst[e])], 1);
    } else {
        // v[i] = sum_h W[i*NH+h]*fcW[h]; thread (i = tx>>3, j = tx&7)
        int i = tx >> 3;
        int j = tx & 7;
        float p = 0.f;
        #pragma unroll
        for (int k = 0; k < 8; ++k)
            p += W[i * NH + j * 8 + k] * fcW[j * 8 + k];
        p += __shfl_xor_sync(0xFFFFFFFFu, p, 1);
        p += __shfl_xor_sync(0xFFFFFFFFu, p, 2);
        p += __shfl_xor_sync(0xFFFFFFFFu, p, 4);
        if (j == 0) g_v[i] = p;
        if (tx == 0) {
            float s = fcb[0];
            #pragma unroll
            for (int h = 0; h < NH; ++h) s += bias[h] * fcW[h];
            g_const = s;
        }
    }
}

// ---------------------------------------------------------------------------
// K2: streaming ydot, 4 float4 per thread (4x MLP). PRE-SYNC: the 4 x-loads
// (input array, no dependency) are issued before cudaGridDependencySynchronize
// so their DRAM latency overlaps K1's execution. POST-SYNC: v/deg reads.
// Triggers AFTER the sync => downstream launch implies K1 complete.
// Leader stores w = dinv_z * y to BOTH g_w and g_acc (self-loop init).
// ---------------------------------------------------------------------------
__global__ void k_ydot(const float* __restrict__ x) {
    const int tx = threadIdx.x;
    const int t0 = blockIdx.x * 1024 + tx;               // < NY
    const float4* xp = reinterpret_cast<const float4*>(x);
    // 4 independent loads front-loaded; overlap with K1 via PDL
    float4 a0 = __ldcs(&xp[t0]);
    float4 a1 = __ldcs(&xp[t0 + 256]);
    float4 a2 = __ldcs(&xp[t0 + 512]);
    float4 a3 = __ldcs(&xp[t0 + 768]);

    cudaGridDependencySynchronize();                     // K1 done: v, deg final
    cudaTriggerProgrammaticLaunchCompletion();

    float4 vv = reinterpret_cast<const float4*>(g_v)[tx & 7];
    float p0 = a0.x * vv.x + a0.y * vv.y + a0.z * vv.z + a0.w * vv.w;
    float p1 = a1.x * vv.x + a1.y * vv.y + a1.z * vv.z + a1.w * vv.w;
    float p2 = a2.x * vv.x + a2.y * vv.y + a2.z * vv.z + a2.w * vv.w;
    float p3 = a3.x * vv.x + a3.y * vv.y + a3.z * vv.z + a3.w * vv.w;
    #pragma unroll
    for (int o = 1; o <= 4; o <<= 1) {
        p0 += __shfl_xor_sync(0xFFFFFFFFu, p0, o);
        p1 += __shfl_xor_sync(0xFFFFFFFFu, p1, o);
        p2 += __shfl_xor_sync(0xFFFFFFFFu, p2, o);
        p3 += __shfl_xor_sync(0xFFFFFFFFu, p3, o);
    }

    if ((tx & 7) == 0) {
        #pragma unroll
        for (int u = 0; u < 4; ++u) {
            int t = t0 + u * 256;
            float p = (u == 0) ? p0 : (u == 1) ? p1 : (u == 2) ? p2 : p3;
            int f = t >> 3;             // row index = b*NZ + z
            int b = f / NZ;
            int z = f - b * NZ;
            float w = p * rsqrtf((float)(g_deg[z] + 1));
            g_w[z * NB + b]   = w;
            g_acc[z * NB + b] = w;      // self-loop init (overwrites old state)
        }
    }
}

// ---------------------------------------------------------------------------
// K3: minimal edge scatter: acc4 += w4[s]. PRE-SYNC: src/dst index loads
// (input arrays) overlap K2. POST-SYNC: w reads + fire-and-forget REDs.
// Triggers AFTER the sync => K4 launch implies K1+K2 complete.
// ---------------------------------------------------------------------------
__global__ void k_scatter(const int* __restrict__ src,
                          const int* __restrict__ dst) {
    int t0 = blockIdx.x * 512 + threadIdx.x;   // t = e*8 + q
    int t1 = t0 + 256;
    int e0 = t0 >> 3, q0 = t0 & 7;
    int e1 = t1 >> 3, q1 = t1 & 7;
    int s0 = __ldg(&src[e0]);
    int d0 = __ldg(&dst[e0]);
    int s1 = __ldg(&src[e1]);
    int d1 = __ldg(&dst[e1]);

    cudaGridDependencySynchronize();                     // K2 done: w final
    cudaTriggerProgrammaticLaunchCompletion();

    float4 m0 = reinterpret_cast<const float4*>(g_w)[s0 * 8 + q0];
    float4 m1 = reinterpret_cast<const float4*>(g_w)[s1 * 8 + q1];
    atomicAdd(&reinterpret_cast<float4*>(g_acc)[d0 * 8 + q0], m0);
    atomicAdd(&reinterpret_cast<float4*>(g_acc)[d1 * 8 + q1], m1);
}

// ---------------------------------------------------------------------------
// K4: out[b][z] = dinv_z * acc[z][b] + const. PRE-SYNC: deg/const reads and
// dinv compute (K1/K2 complete before this kernel can launch, since K3
// triggers after its own sync). POST-SYNC: acc reads, transpose, store.
// Self-cleans g_deg (acc is overwritten by k_ydot next execution).
// ---------------------------------------------------------------------------
__global__ void k_out(float* __restrict__ out) {
    __shared__ float tile[32][33];
    const int tx = threadIdx.x;
    const int zb = blockIdx.x * 32;           // NZ % 32 == 0 (4000 = 125*32)

    int zi = tx >> 3;
    int q  = tx & 7;
    int z  = zb + zi;
    int ridx = z * 8 + q;                     // float4 index into acc rows
    float dinv = rsqrtf((float)(g_deg[z] + 1));   // deg final (K1 done)
    float c = g_const;

    cudaGridDependencySynchronize();                     // K3 done: acc final

    float4 a4 = reinterpret_cast<const float4*>(g_acc)[ridx];
    tile[zi][q * 4 + 0] = dinv * a4.x;
    tile[zi][q * 4 + 1] = dinv * a4.y;
    tile[zi][q * 4 + 2] = dinv * a4.z;
    tile[zi][q * 4 + 3] = dinv * a4.w;
    __syncthreads();

    // self-clean deg (all reads happened before the sync)
    if (tx < 32) g_deg[zb + tx] = 0;

    // write side: thread (b = tx>>3, zq = tx&7) writes out[b][zb+4zq .. +3]
    int b  = tx >> 3;
    int zq = tx & 7;
    float4 o;
    o.x = tile[zq * 4 + 0][b] + c;
    o.y = tile[zq * 4 + 1][b] + c;
    o.z = tile[zq * 4 + 2][b] + c;
    o.w = tile[zq * 4 + 3][b] + c;
    reinterpret_cast<float4*>(out)[((size_t)b * NZ + zb) / 4 + zq] = o;
}

// ---------------------------------------------------------------------------
static inline void launch_pdl(void* fn, dim3 grid, dim3 block,
                              void** args) {
    cudaLaunchConfig_t cfg = {};
    cfg.gridDim = grid;
    cfg.blockDim = block;
    cfg.dynamicSmemBytes = 0;
    cfg.stream = 0;
    cudaLaunchAttribute attr[1];
    attr[0].id = cudaLaunchAttributeProgrammaticStreamSerialization;
    attr[0].val.programmaticStreamSerializationAllowed = 1;
    cfg.attrs = attr;
    cfg.numAttrs = 1;
    cudaLaunchKernelExC(&cfg, fn, args);
}

extern "C" void kernel_launch(void* const* d_in, const int* in_sizes, int n_in,
                              void* d_out, int out_size) {
    const float* x    = (const float*)d_in[0];   // [32,4000,32]
    const int*   ei   = (const int*)  d_in[1];   // [2,64000]
    const float* W    = (const float*)d_in[2];   // [32,64]
    const float* bias = (const float*)d_in[3];   // [64]
    const float* fcW  = (const float*)d_in[4];   // [64]
    const float* fcb  = (const float*)d_in[5];   // [1]
    float* out = (float*)d_out;                  // [32,4000]

    const int* src = ei;
    const int* dst = ei + NE;

    // K1: normal launch
    k_hist_v<<<NEB + 1, 256>>>(dst, W, bias, fcW, fcb);

    // K2..K4: programmatic dependent launches (overlap ramps/preambles)
    {
        void* a[] = { (void*)&x };
        launch_pdl((void*)k_ydot, dim3(NYB), dim3(256), a);
    }
    {
        void* a[] = { (void*)&src, (void*)&dst };
        launch_pdl((void*)k_scatter, dim3(NSB), dim3(256), a);
    }
    {
        void* a[] = { (void*)&out };
        launch_pdl((void*)k_out, dim3(NZ / 32), dim3(256), a);
    }
}